// round 15
// baseline (speedup 1.0000x reference)
#include <cuda_runtime.h>

#define K 32
#define NELEM (32*64*1024)
#define THREADS 128
#define GRID 592          // 148 x 4 CTAs = one wave
#define LUTN 2048
#define FULL 0xffffffffu

typedef unsigned long long u64;

// Global accumulators; last block self-cleans for graph replay.
__device__ float g_P[K];
__device__ float g_Q;
__device__ unsigned int g_count;

__device__ __forceinline__ float ex2f_(float x) {
    float r; asm("ex2.approx.ftz.f32 %0, %1;" : "=f"(r) : "f"(x)); return r;
}
__device__ __forceinline__ float rsqf_(float x) {
    float r; asm("rsqrt.approx.ftz.f32 %0, %1;" : "=f"(r) : "f"(x)); return r;
}
__device__ __forceinline__ u64 pack2(float lo, float hi) {
    u64 r; asm("mov.b64 %0, {%1, %2};" : "=l"(r) : "f"(lo), "f"(hi)); return r;
}
__device__ __forceinline__ float lo2(u64 v) {
    float lo, hi; asm("mov.b64 {%0, %1}, %2;" : "=f"(lo), "=f"(hi) : "l"(v)); return lo;
}
__device__ __forceinline__ float hi2(u64 v) {
    float lo, hi; asm("mov.b64 {%0, %1}, %2;" : "=f"(lo), "=f"(hi) : "l"(v)); return hi;
}
#define MUL2(o, a, b) asm("mul.rn.f32x2 %0, %1, %2;" : "=l"(o) : "l"(a), "l"(b))
#define ADD2(o, a, b) asm("add.rn.f32x2 %0, %1, %2;" : "=l"(o) : "l"(a), "l"(b))

// Monotone cell map; MUST be used identically for bins (LUT build) and x.
__device__ __forceinline__ int cellof(float v, float blo, float scl) {
    float cf = fminf(fmaxf((v - blo) * scl, 0.0f), (float)(LUTN - 1));
    return (int)cf;
}

__global__ __launch_bounds__(THREADS, 4)
void ssq_kernel(const float* __restrict__ x,
                const float* __restrict__ bins,
                float* __restrict__ out)
{
    __shared__ float sbins[K + 8];         // sorted bins + +inf pad (refine-safe)
    __shared__ int   sBinCell[K];
    __shared__ float4 sTabP[K + 1];        // {P10, P5, PB, 0} exclusive prefixes
    __shared__ float4 sTabQ[K + 1];        // {Q10, Q5, QB, 0} inclusive suffixes
    __shared__ float sEpsB, sLo, sScale;
    __shared__ unsigned char sLUT[LUTN];   // #{cell(b) < c}
    __shared__ float sRed[THREADS/32][K];
    __shared__ float sQw[THREADS/32];
    __shared__ int   sLast;

    const int tid  = threadIdx.x;
    const int lane = tid & 31;
    const int warp = tid >> 5;

    const float C5  = 7.21347520444482f;    // 5*log2(e)
    const float C10 = 14.42695040888963f;   // 10*log2(e)

    // ---- Prologue (warp 0): sort bins, build packed prefix/suffix tables ----
    if (warp == 0) {
        float v = __ldg(&bins[lane]);
        #pragma unroll
        for (int kk = 2; kk <= 32; kk <<= 1) {
            #pragma unroll
            for (int j = kk >> 1; j > 0; j >>= 1) {
                float w = __shfl_xor_sync(FULL, v, j);
                bool takeMin = (((lane & j) == 0) == ((lane & kk) == 0));
                v = takeMin ? fminf(v, w) : fmaxf(v, w);
            }
        }
        sbins[lane] = v;               // ascending
        if (lane < 8) sbins[K + lane] = 3.0e38f;

        float bmin = __shfl_sync(FULL, v, 0);
        float bmax = __shfl_sync(FULL, v, 31);

        float sb = v;
        #pragma unroll
        for (int m = 16; m > 0; m >>= 1) sb += __shfl_xor_sync(FULL, sb, m);
        if (lane == 0) {
            sEpsB = 1e-10f * sb;
            sLo = bmin;
            sScale = (float)LUTN / (bmax - bmin + 1e-20f);
        }
        __syncwarp();
        sBinCell[lane] = cellof(v, sLo, sScale);

        float e10 = ex2f_( C10 * v), f10 = ex2f_(-C10 * v);
        float e5  = ex2f_( C5  * v), f5  = ex2f_(-C5  * v);
        float eb  = e10 * v,         fb  = f10 * v;

        float p10 = e10, p5 = e5, pb = eb;          // inclusive prefix
        #pragma unroll
        for (int d = 1; d < 32; d <<= 1) {
            float t0 = __shfl_up_sync(FULL, p10, d);
            float t1 = __shfl_up_sync(FULL, p5,  d);
            float t2 = __shfl_up_sync(FULL, pb,  d);
            if (lane >= d) { p10 += t0; p5 += t1; pb += t2; }
        }
        float q10 = f10, q5 = f5, qb = fb;          // inclusive suffix
        #pragma unroll
        for (int d = 1; d < 32; d <<= 1) {
            float t0 = __shfl_down_sync(FULL, q10, d);
            float t1 = __shfl_down_sync(FULL, q5,  d);
            float t2 = __shfl_down_sync(FULL, qb,  d);
            if (lane + d < 32) { q10 += t0; q5 += t1; qb += t2; }
        }
        sTabP[lane + 1] = make_float4(p10, p5, pb, 0.f);
        sTabQ[lane]     = make_float4(q10, q5, qb, 0.f);
        if (lane == 0) {
            sTabP[0] = make_float4(0.f, 0.f, 0.f, 0.f);
            sTabQ[K] = make_float4(0.f, 0.f, 0.f, 0.f);
        }
    }
    __syncthreads();

    // ---- LUT build (whole block): LUT[c] = #{cell(b_k) < c} ----
    for (int c = tid; c < LUTN; c += THREADS) {
        int r = 0;
        #pragma unroll
        for (int k = 0; k < K; k++) r += (sBinCell[k] < c) ? 1 : 0;
        sLUT[c] = (unsigned char)r;
    }

    // Per-thread packed constants: {exp(10 b_2j), exp(10 b_2j+1)} and negatives.
    u64 c10p[K/2], d10p[K/2];
    #pragma unroll
    for (int j = 0; j < K/2; j++) {
        float b0 = sbins[2*j], b1 = sbins[2*j+1];
        c10p[j] = pack2(ex2f_( C10 * b0), ex2f_( C10 * b1));
        d10p[j] = pack2(ex2f_(-C10 * b0), ex2f_(-C10 * b1));
    }
    __syncthreads();

    u64 sumP2[K/2];
    #pragma unroll
    for (int j = 0; j < K/2; j++) sumP2[j] = 0ull;
    float qacc = 0.f;

    const float epsB = sEpsB;
    const float blo  = sLo;
    const float scl  = sScale;

    const int gtid = blockIdx.x * THREADS + tid;
    const int s = GRID * THREADS;
    const float4* x4 = (const float4*)x;
    float4* o4 = (float4*)out;
    const int n4 = NELEM / 4;
    const float4 z4 = make_float4(0.f, 0.f, 0.f, 0.f);

    int i = gtid;
    float4 cur = (i < n4) ? x4[i] : z4;
    while (i < n4) {
        const int nj = i + s;
        float4 nxt = (nj < n4) ? x4[nj] : z4;

        float xs[4] = {cur.x, cur.y, cur.z, cur.w};
        float os[4];
        #pragma unroll
        for (int c = 0; c < 4; c++) {
            const float xe = xs[c];
            // Branch-free exact rank: LUT + 4 independent predicated compares.
            const int mlo = sLUT[cellof(xe, blo, scl)];
            int m = mlo;
            m += (sbins[mlo]     <= xe) ? 1 : 0;
            m += (sbins[mlo + 1] <= xe) ? 1 : 0;
            m += (sbins[mlo + 2] <= xe) ? 1 : 0;
            m += (sbins[mlo + 3] <= xe) ? 1 : 0;

            const float na = -C5 * xe;
            const float A  = ex2f_(na);        // exp(-5x)
            const float B  = ex2f_(-na);       // exp(+5x)
            const float A2 = A * A;
            const float B2 = B * B;

            const float4 tp = sTabP[m];
            const float4 tq = sTabQ[m];
            const float S  = fmaf(A2, tp.x, B2 * tq.x);
            const float Hs = fmaf(A,  tp.y, B  * tq.y);
            const float bR = fmaf(A2, tp.z, B2 * tq.z);
            const float rs = rsqf_(S);
            const float invS = rs * rs;
            qacc  = fmaf(Hs, rs, qacc);
            os[c] = fmaf(bR, invS, epsB);

            // sumP_k += soft_k = min(A2*invS*e10_k, B2*invS*f10_k), registers only.
            const float ai = A2 * invS;
            const float bi = B2 * invS;
            const u64 ais = pack2(ai, ai);
            const u64 bis = pack2(bi, bi);
            #pragma unroll
            for (int j = 0; j < K/2; j++) {
                u64 u, v;
                MUL2(u, ais, c10p[j]);
                MUL2(v, bis, d10p[j]);
                float e0 = fminf(lo2(u), lo2(v));   // FMNMX (alu pipe)
                float e1 = fminf(hi2(u), hi2(v));
                u64 e = pack2(e0, e1);
                ADD2(sumP2[j], sumP2[j], e);
            }
        }
        o4[i] = make_float4(os[0], os[1], os[2], os[3]);
        cur = nxt; i = nj;
    }

    // ---- Block reduce ----
    #pragma unroll
    for (int m = 16; m > 0; m >>= 1) {
        qacc += __shfl_xor_sync(FULL, qacc, m);
        #pragma unroll
        for (int j = 0; j < K/2; j++) {
            u64 o = __shfl_xor_sync(FULL, sumP2[j], m);
            ADD2(sumP2[j], sumP2[j], o);
        }
    }
    if (lane == 0) {
        #pragma unroll
        for (int j = 0; j < K/2; j++) {
            sRed[warp][2*j]   = lo2(sumP2[j]);
            sRed[warp][2*j+1] = hi2(sumP2[j]);
        }
        sQw[warp] = qacc;
    }
    __syncthreads();
    if (tid < K) {
        float t = 0.f;
        #pragma unroll
        for (int w = 0; w < THREADS/32; w++) t += sRed[w][tid];
        atomicAdd(&g_P[tid], t);
    }
    if (tid == 0) {
        float q = 0.f;
        #pragma unroll
        for (int w = 0; w < THREADS/32; w++) q += sQw[w];
        atomicAdd(&g_Q, q);
    }

    // ---- Last-block finalize (self-cleaning) ----
    if (tid == 0) {
        __threadfence();
        unsigned int arrived = atomicAdd(&g_count, 1u);
        sLast = (arrived == GRID - 1u) ? 1 : 0;
    }
    __syncthreads();
    if (sLast) {
        __threadfence();
        if (tid < 32) {
            const float invN = 1.0f / (float)NELEM;
            volatile float* gp = g_P;
            float p = fmaf(gp[lane], invN, 1e-10f);   // mean(soft_k) + EPS
            float e = -p * logf(p);
            #pragma unroll
            for (int d = 16; d > 0; d >>= 1)
                e += __shfl_xor_sync(FULL, e, d);
            if (lane == 0) {
                volatile float* vq = &g_Q;
                out[NELEM]     = e;                              // code entropy
                out[NELEM + 1] = 0.f;                            // TAU
                out[NELEM + 2] = vq[0] * (1.0f / (float)NELEM);  // quant loss
                out[NELEM + 3] = 0.f;                            // TAU2
            }
        }
        __syncthreads();
        if (tid < K) g_P[tid] = 0.f;
        if (tid == 0) { g_Q = 0.f; g_count = 0u; }
    }
}

extern "C" void kernel_launch(void* const* d_in, const int* in_sizes, int n_in,
                              void* d_out, int out_size)
{
    const float* x    = (const float*)d_in[0];
    const float* bins = (const float*)d_in[1];
    if (n_in >= 2 && in_sizes[0] == K && in_sizes[1] != K) {
        const float* tmp = x; x = bins; bins = tmp;
    }
    float* out = (float*)d_out;

    ssq_kernel<<<GRID, THREADS>>>(x, bins, out);
}